// round 16
// baseline (speedup 1.0000x reference)
#include <cuda_runtime.h>
#include <cuda_bf16.h>
#include <cstdint>

// Problem dims (fixed by the dataset)
#define MDIM 4096
#define NDIM 4096
#define KDIM 4096

#define BM 128
#define BN 256
#define BK 32
#define LD 40   // smem row stride in bf16 (80B): ldmatrix rows hit distinct banks
#define NKIT (KDIM / BK)
#define NTHR 256

#define A_STAGE_B (BM * LD * 2)                    // 10240 B
#define B_STAGE_B (BN * LD * 2)                    // 20480 B
#define SMEM_TOT  (2 * A_STAGE_B + 2 * B_STAGE_B)  // 61440 B (dynamic)

// Pre-pass grid split (fused kernel)
#define QDQ_BLOCKS (MDIM * KDIM / 16 / 256)        // 4096
#define WDQ_BLOCKS (NDIM * KDIM / 16 / 256)        // 4096

// Scratch: precomputed bf16 operands (proven safe since R4).
__device__ __nv_bfloat16 g_xq[(size_t)MDIM * KDIM];   // 32 MB
__device__ __nv_bfloat16 g_w [(size_t)NDIM * KDIM];   // 32 MB

__device__ __forceinline__ float exp2i(int e) {
    return __uint_as_float((uint32_t)(e + 127) << 23);
}
__device__ __forceinline__ float q_e2m1(float v) {
    float mag = fabsf(v);
    float q;
    if (mag <= 2.0f)      q = rintf(mag + mag) * 0.5f;
    else if (mag < 4.0f)  q = rintf(mag);
    else                  q = fminf(rintf(mag * 0.5f) * 2.0f, 6.0f);
    return copysignf(q, v);
}
__device__ __forceinline__ float dec_e2m1(uint32_t nib) {
    uint32_t j = nib & 7u;
    uint32_t bits = (j >= 2u) ? (((126u + (j >> 1)) << 23) | ((j & 1u) << 22))
                              : (j * 0x3F000000u);
    bits |= (nib & 8u) << 28;
    return __uint_as_float(bits);
}
__device__ __forceinline__ uint32_t pack2(float a, float b) {
    return (uint32_t)__bfloat16_as_ushort(__float2bfloat16(a)) |
           ((uint32_t)__bfloat16_as_ushort(__float2bfloat16(b)) << 16);
}

// ------- Fused pre-pass: qdq(x) (blocks [0,4096)) + wdq (blocks [4096,8192)) -
__global__ void prep_kernel(const float* __restrict__ X,
                            const int* __restrict__ WP,
                            const int* __restrict__ WS) {
    if (blockIdx.x < QDQ_BLOCKS) {
        size_t t = (size_t)blockIdx.x * blockDim.x + threadIdx.x;
        const float4* xq = (const float4*)(X + 16 * t);
        float4 xv0 = xq[0], xv1 = xq[1], xv2 = xq[2], xv3 = xq[3];
        float f[16] = { xv0.x, xv0.y, xv0.z, xv0.w, xv1.x, xv1.y, xv1.z, xv1.w,
                        xv2.x, xv2.y, xv2.z, xv2.w, xv3.x, xv3.y, xv3.z, xv3.w };
        float m = 0.0f;
        #pragma unroll
        for (int i = 0; i < 16; i++) m = fmaxf(m, fabsf(f[i]));
        m = fmaxf(m, __shfl_xor_sync(0xffffffffu, m, 1));   // partner half-block
        int e  = ((int)(__float_as_uint(m) >> 23) & 0xFF) - 127;
        int eu = e - 2;
        if (eu < -126) eu = -126;
        const float scl = exp2i(eu), inv = exp2i(-eu);
        uint32_t pk[8];
        #pragma unroll
        for (int i = 0; i < 8; i++)
            pk[i] = pack2(q_e2m1(f[2*i] * inv) * scl, q_e2m1(f[2*i+1] * inv) * scl);
        uint4* dst = (uint4*)(g_xq + 16 * t);
        dst[0] = make_uint4(pk[0], pk[1], pk[2], pk[3]);
        dst[1] = make_uint4(pk[4], pk[5], pk[6], pk[7]);
    } else {
        size_t t = (size_t)(blockIdx.x - QDQ_BLOCKS) * blockDim.x + threadIdx.x;
        const int4* wq = (const int4*)(WP + 8 * t);
        int4 wv0 = wq[0], wv1 = wq[1];
        int sv = WS[t >> 1];
        int ei = sv - 127;
        float bs = (ei < -126) ? __uint_as_float(0x00400000u) : exp2i(ei);
        int wvv[8] = { wv0.x, wv0.y, wv0.z, wv0.w, wv1.x, wv1.y, wv1.z, wv1.w };
        uint32_t pk[8];
        #pragma unroll
        for (int i = 0; i < 8; i++) {
            uint32_t byte = (uint32_t)wvv[i] & 0xFFu;
            pk[i] = pack2(dec_e2m1(byte & 0xFu) * bs, dec_e2m1((byte >> 4) & 0xFu) * bs);
        }
        uint4* dst = (uint4*)(g_w + 16 * t);
        dst[0] = make_uint4(pk[0], pk[1], pk[2], pk[3]);
        dst[1] = make_uint4(pk[4], pk[5], pk[6], pk[7]);
    }
}

// ---- Kernel 3: GEMM 128x256, 256 thr (2x4 warps of 64x64), cp.async.ca -----
// R15's proven async 2-stage pipeline on R7's wider tile: 24KB copied per
// iter for TWO tile-outputs -> per-output L1 wavefronts drop 384 -> 352.
__device__ __forceinline__ void ldsm_x4(uint32_t* r, uint32_t addr) {
    asm volatile("ldmatrix.sync.aligned.m8n8.x4.shared.b16 {%0,%1,%2,%3}, [%4];"
                 : "=r"(r[0]), "=r"(r[1]), "=r"(r[2]), "=r"(r[3]) : "r"(addr));
}
__device__ __forceinline__ void cpa16(uint32_t dst, const void* src) {
    asm volatile("cp.async.ca.shared.global [%0], [%1], 16;" :: "r"(dst), "l"(src));
}
#define CPA_COMMIT() asm volatile("cp.async.commit_group;" ::: "memory")
#define CPA_WAIT0()  asm volatile("cp.async.wait_group 0;" ::: "memory")

__global__ __launch_bounds__(NTHR, 1) void gemm_kernel(float* __restrict__ C) {
    extern __shared__ __align__(128) char smem[];
    __nv_bfloat16* sA0 = (__nv_bfloat16*)smem;
    __nv_bfloat16* sB0 = (__nv_bfloat16*)(smem + 2 * A_STAGE_B);

    const int tid  = threadIdx.x;
    const int lane = tid & 31;
    const int warp = tid >> 5;
    const int wm = warp >> 2, wn = warp & 3;       // 2x4 warps: 64 rows x 64 cols each
    const int g  = lane >> 2, tg = lane & 3;
    const int bM = blockIdx.y * BM, bN = blockIdx.x * BN;

    // ---- loader offsets (16B chunks; R14 row remap kept: 4-lane contiguous
    // 64B row segments, conflict-free phase pairing) ----
    const __nv_bfloat16* Abase = g_xq + (size_t)bM * KDIM;
    const __nv_bfloat16* Bbase = g_w  + (size_t)bN * KDIM;
    const uint32_t sbase = (uint32_t)__cvta_generic_to_shared(smem);
    uint32_t aoff[2], dstA[2], boff[4], dstB[4];
    #pragma unroll
    for (int j = 0; j < 2; j++) {     // A: 512 chunks, 2/thread
        int c = tid + j * NTHR, r0 = c >> 2, ch = c & 3;
        int r = (r0 & ~7) | ((r0 & 1) << 2) | ((r0 >> 1) & 3);
        aoff[j] = r * KDIM + ch * 8;
        dstA[j] = sbase + (uint32_t)(r * LD + ch * 8) * 2u;
    }
    #pragma unroll
    for (int j = 0; j < 4; j++) {     // B: 1024 chunks, 4/thread
        int c = tid + j * NTHR, r0 = c >> 2, ch = c & 3;
        int r = (r0 & ~7) | ((r0 & 1) << 2) | ((r0 >> 1) & 3);
        boff[j] = r * KDIM + ch * 8;
        dstB[j] = sbase + 2 * A_STAGE_B + (uint32_t)(r * LD + ch * 8) * 2u;
    }

    // ---- ldmatrix lane coords (proven R7) ----
    const int rowA = ((lane >> 3) & 1) * 8 + (lane & 7);
    const int colA = (lane >> 4) * 8;
    const int rowB = ((lane >> 4) & 1) * 8 + (lane & 7);
    const int colB = ((lane >> 3) & 1) * 8;
    uint32_t saddrA[2], saddrB[2];
    #pragma unroll
    for (int s = 0; s < 2; s++) {
        saddrA[s] = (uint32_t)__cvta_generic_to_shared(
            sA0 + s * (A_STAGE_B / 2) + (wm * 64 + rowA) * LD + colA);
        saddrB[s] = (uint32_t)__cvta_generic_to_shared(
            sB0 + s * (B_STAGE_B / 2) + (wn * 64 + rowB) * LD + colB);
    }

    // ---- prologue: fill stage 0 ----
    #pragma unroll
    for (int j = 0; j < 2; j++) cpa16(dstA[j], Abase + aoff[j]);
    #pragma unroll
    for (int j = 0; j < 4; j++) cpa16(dstB[j], Bbase + boff[j]);
    CPA_COMMIT();
    CPA_WAIT0();
    __syncthreads();

    float acc[4][8][4];
    #pragma unroll
    for (int i = 0; i < 4; i++)
        #pragma unroll
        for (int j = 0; j < 8; j++)
            #pragma unroll
            for (int r = 0; r < 4; r++) acc[i][j][r] = 0.0f;

    for (int kt = 0; kt < NKIT; kt++) {
        const int s = kt & 1;

        // Fill stage s^1 with tile kt+1 (readers done at iter kt-1, before the
        // barrier that admitted us — two-stage invariant). The mma block below
        // covers the copy latency.
        if (kt + 1 < NKIT) {
            const int k0 = (kt + 1) * BK;
            const uint32_t sa = (uint32_t)((s ^ 1) * A_STAGE_B);
            const uint32_t sb = (uint32_t)((s ^ 1) * B_STAGE_B);
            #pragma unroll
            for (int j = 0; j < 2; j++) cpa16(dstA[j] + sa, Abase + aoff[j] + k0);
            #pragma unroll
            for (int j = 0; j < 4; j++) cpa16(dstB[j] + sb, Bbase + boff[j] + k0);
        }
        CPA_COMMIT();

        #pragma unroll
        for (int kk = 0; kk < 2; kk++) {
            uint32_t a[4][4], b[4][4];
            #pragma unroll
            for (int ti = 0; ti < 4; ti++)
                ldsm_x4(a[ti], saddrA[s] + (uint32_t)(ti * 16 * LD + kk * 16) * 2u);
            #pragma unroll
            for (int p = 0; p < 4; p++)     // pair p covers n8-tiles 2p, 2p+1
                ldsm_x4(b[p], saddrB[s] + (uint32_t)(p * 16 * LD + kk * 16) * 2u);
            #pragma unroll
            for (int ti = 0; ti < 4; ti++) {
                #pragma unroll
                for (int tj = 0; tj < 8; tj++) {
                    const int p = tj >> 1, h = (tj & 1) * 2;
                    asm volatile(
                        "mma.sync.aligned.m16n8k16.row.col.f32.bf16.bf16.f32 "
                        "{%0,%1,%2,%3}, {%4,%5,%6,%7}, {%8,%9}, {%0,%1,%2,%3};\n"
                        : "+f"(acc[ti][tj][0]), "+f"(acc[ti][tj][1]),
                          "+f"(acc[ti][tj][2]), "+f"(acc[ti][tj][3])
                        : "r"(a[ti][0]), "r"(a[ti][1]), "r"(a[ti][2]), "r"(a[ti][3]),
                          "r"(b[p][h]), "r"(b[p][h + 1]));
                }
            }
        }

        // Stage s^1 copy complete, then publish to all warps.
        CPA_WAIT0();
        __syncthreads();
    }

    #pragma unroll
    for (int ti = 0; ti < 4; ti++) {
        #pragma unroll
        for (int tj = 0; tj < 8; tj++) {
            int r = bM + wm * 64 + ti * 16 + g;
            int c = bN + wn * 64 + tj * 8 + tg * 2;
            float2 lo = make_float2(acc[ti][tj][0], acc[ti][tj][1]);
            float2 hi = make_float2(acc[ti][tj][2], acc[ti][tj][3]);
            *reinterpret_cast<float2*>(&C[(size_t)r * NDIM + c]) = lo;
            *reinterpret_cast<float2*>(&C[(size_t)(r + 8) * NDIM + c]) = hi;
        }
    }
}

// ---------------------------------------------------------------------------
extern "C" void kernel_launch(void* const* d_in, const int* in_sizes, int n_in,
                              void* d_out, int out_size) {
    const float* x  = nullptr;
    const int*   wp = nullptr;
    const int*   ws = nullptr;
    for (int i = 0; i < n_in; i++) {
        if      (in_sizes[i] == MDIM * KDIM)      x  = (const float*)d_in[i];
        else if (in_sizes[i] == NDIM * KDIM / 2)  wp = (const int*)d_in[i];
        else if (in_sizes[i] == NDIM * KDIM / 32) ws = (const int*)d_in[i];
    }
    if (!x || !wp || !ws) {
        x  = (const float*)d_in[0];
        wp = (const int*)d_in[1];
        ws = (const int*)d_in[2];
    }

    // Fused pre-pass: one launch covers qdq(x) and wdq(W).
    prep_kernel<<<QDQ_BLOCKS + WDQ_BLOCKS, 256>>>(x, wp, ws);

    cudaFuncSetAttribute(gemm_kernel, cudaFuncAttributeMaxDynamicSharedMemorySize, SMEM_TOT);
    dim3 grid(NDIM / BN, MDIM / BM);
    gemm_kernel<<<grid, NTHR, SMEM_TOT>>>((float*)d_out);
}

// round 17
// speedup vs baseline: 1.9004x; 1.9004x over previous
#include <cuda_runtime.h>
#include <cuda_bf16.h>
#include <cstdint>

// Problem dims (fixed by the dataset)
#define MDIM 4096
#define NDIM 4096
#define KDIM 4096

#define BM 128
#define BN 128
#define BK 64
#define LD 72   // smem row stride in bf16 (144B): ldsm rows hit banks {0,16,..112}
#define NKIT (KDIM / BK)
#define NTHR 128

#define A_STAGE_B (BM * LD * 2)                    // 18432 B
#define B_STAGE_B (BN * LD * 2)                    // 18432 B
#define SMEM_TOT  (2 * A_STAGE_B + 2 * B_STAGE_B)  // 73728 B (dynamic; occ2=147KB<=228KB)

// Pre-pass grid split (fused kernel)
#define QDQ_BLOCKS (MDIM * KDIM / 16 / 256)        // 4096
#define WDQ_BLOCKS (NDIM * KDIM / 16 / 256)        // 4096

// Scratch: precomputed bf16 operands (proven safe since R4).
__device__ __nv_bfloat16 g_xq[(size_t)MDIM * KDIM];   // 32 MB
__device__ __nv_bfloat16 g_w [(size_t)NDIM * KDIM];   // 32 MB

__device__ __forceinline__ float exp2i(int e) {
    return __uint_as_float((uint32_t)(e + 127) << 23);
}
__device__ __forceinline__ float q_e2m1(float v) {
    float mag = fabsf(v);
    float q;
    if (mag <= 2.0f)      q = rintf(mag + mag) * 0.5f;
    else if (mag < 4.0f)  q = rintf(mag);
    else                  q = fminf(rintf(mag * 0.5f) * 2.0f, 6.0f);
    return copysignf(q, v);
}
__device__ __forceinline__ float dec_e2m1(uint32_t nib) {
    uint32_t j = nib & 7u;
    uint32_t bits = (j >= 2u) ? (((126u + (j >> 1)) << 23) | ((j & 1u) << 22))
                              : (j * 0x3F000000u);
    bits |= (nib & 8u) << 28;
    return __uint_as_float(bits);
}
__device__ __forceinline__ uint32_t pack2(float a, float b) {
    return (uint32_t)__bfloat16_as_ushort(__float2bfloat16(a)) |
           ((uint32_t)__bfloat16_as_ushort(__float2bfloat16(b)) << 16);
}

// ------- Fused pre-pass: qdq(x) (blocks [0,4096)) + wdq (blocks [4096,8192)) -
__global__ void prep_kernel(const float* __restrict__ X,
                            const int* __restrict__ WP,
                            const int* __restrict__ WS) {
    if (blockIdx.x < QDQ_BLOCKS) {
        size_t t = (size_t)blockIdx.x * blockDim.x + threadIdx.x;
        const float4* xq = (const float4*)(X + 16 * t);
        float4 xv0 = xq[0], xv1 = xq[1], xv2 = xq[2], xv3 = xq[3];
        float f[16] = { xv0.x, xv0.y, xv0.z, xv0.w, xv1.x, xv1.y, xv1.z, xv1.w,
                        xv2.x, xv2.y, xv2.z, xv2.w, xv3.x, xv3.y, xv3.z, xv3.w };
        float m = 0.0f;
        #pragma unroll
        for (int i = 0; i < 16; i++) m = fmaxf(m, fabsf(f[i]));
        m = fmaxf(m, __shfl_xor_sync(0xffffffffu, m, 1));   // partner half-block
        int e  = ((int)(__float_as_uint(m) >> 23) & 0xFF) - 127;
        int eu = e - 2;
        if (eu < -126) eu = -126;
        const float scl = exp2i(eu), inv = exp2i(-eu);
        uint32_t pk[8];
        #pragma unroll
        for (int i = 0; i < 8; i++)
            pk[i] = pack2(q_e2m1(f[2*i] * inv) * scl, q_e2m1(f[2*i+1] * inv) * scl);
        uint4* dst = (uint4*)(g_xq + 16 * t);
        dst[0] = make_uint4(pk[0], pk[1], pk[2], pk[3]);
        dst[1] = make_uint4(pk[4], pk[5], pk[6], pk[7]);
    } else {
        size_t t = (size_t)(blockIdx.x - QDQ_BLOCKS) * blockDim.x + threadIdx.x;
        const int4* wq = (const int4*)(WP + 8 * t);
        int4 wv0 = wq[0], wv1 = wq[1];
        int sv = WS[t >> 1];
        int ei = sv - 127;
        float bs = (ei < -126) ? __uint_as_float(0x00400000u) : exp2i(ei);
        int wvv[8] = { wv0.x, wv0.y, wv0.z, wv0.w, wv1.x, wv1.y, wv1.z, wv1.w };
        uint32_t pk[8];
        #pragma unroll
        for (int i = 0; i < 8; i++) {
            uint32_t byte = (uint32_t)wvv[i] & 0xFFu;
            pk[i] = pack2(dec_e2m1(byte & 0xFu) * bs, dec_e2m1((byte >> 4) & 0xFu) * bs);
        }
        uint4* dst = (uint4*)(g_w + 16 * t);
        dst[0] = make_uint4(pk[0], pk[1], pk[2], pk[3]);
        dst[1] = make_uint4(pk[4], pk[5], pk[6], pk[7]);
    }
}

// ---- Kernel 3: GEMM 128x128, occ 2, cp.async.ca, BK=64 (half the syncs) ----
__device__ __forceinline__ void ldsm_x4(uint32_t* r, uint32_t addr) {
    asm volatile("ldmatrix.sync.aligned.m8n8.x4.shared.b16 {%0,%1,%2,%3}, [%4];"
                 : "=r"(r[0]), "=r"(r[1]), "=r"(r[2]), "=r"(r[3]) : "r"(addr));
}
__device__ __forceinline__ void cpa16(uint32_t dst, const void* src) {
    asm volatile("cp.async.ca.shared.global [%0], [%1], 16;" :: "r"(dst), "l"(src));
}
#define CPA_COMMIT() asm volatile("cp.async.commit_group;" ::: "memory")
#define CPA_WAIT0()  asm volatile("cp.async.wait_group 0;" ::: "memory")

__global__ __launch_bounds__(NTHR, 2) void gemm_kernel(float* __restrict__ C) {
    extern __shared__ __align__(128) char smem[];
    __nv_bfloat16* sA0 = (__nv_bfloat16*)smem;
    __nv_bfloat16* sB0 = (__nv_bfloat16*)(smem + 2 * A_STAGE_B);

    const int tid  = threadIdx.x;
    const int lane = tid & 31;
    const int warp = tid >> 5;
    const int wm = warp >> 1, wn = warp & 1;       // 2x2 warps: 64 rows x 64 cols each
    const int g  = lane >> 2, tg = lane & 3;
    const int bM = blockIdx.y * BM, bN = blockIdx.x * BN;

    // ---- loader offsets (16B chunks; BK=64 -> a row is 8 chunks = 128B, so
    // 8 consecutive lanes cover exactly one row: global reads coalesced and
    // smem writes hit 32 distinct banks per phase — conflict-free naturally) --
    const __nv_bfloat16* Abase = g_xq + (size_t)bM * KDIM;
    const __nv_bfloat16* Bbase = g_w  + (size_t)bN * KDIM;
    const uint32_t sbase = (uint32_t)__cvta_generic_to_shared(smem);
    uint32_t off[8], dstA[8], dstB[8];
    #pragma unroll
    for (int j = 0; j < 8; j++) {     // A: 1024 chunks (8/thread); B identical map
        int c = tid + j * NTHR, r = c >> 3, ch = c & 7;
        off[j]  = r * KDIM + ch * 8;
        uint32_t so = (uint32_t)(r * LD + ch * 8) * 2u;
        dstA[j] = sbase + so;                       // + s*A_STAGE_B
        dstB[j] = sbase + 2 * A_STAGE_B + so;       // + s*B_STAGE_B
    }

    // ---- ldmatrix lane coords (proven R7/R9) ----
    const int rowA = ((lane >> 3) & 1) * 8 + (lane & 7);
    const int colA = (lane >> 4) * 8;
    const int rowB = ((lane >> 4) & 1) * 8 + (lane & 7);
    const int colB = ((lane >> 3) & 1) * 8;
    uint32_t saddrA[2], saddrB[2];
    #pragma unroll
    for (int s = 0; s < 2; s++) {
        saddrA[s] = (uint32_t)__cvta_generic_to_shared(
            sA0 + s * (A_STAGE_B / 2) + (wm * 64 + rowA) * LD + colA);
        saddrB[s] = (uint32_t)__cvta_generic_to_shared(
            sB0 + s * (B_STAGE_B / 2) + (wn * 64 + rowB) * LD + colB);
    }

    // ---- prologue: fill stage 0 ----
    #pragma unroll
    for (int j = 0; j < 8; j++) {
        cpa16(dstA[j], Abase + off[j]);
        cpa16(dstB[j], Bbase + off[j]);
    }
    CPA_COMMIT();
    CPA_WAIT0();
    __syncthreads();

    float acc[4][8][4];
    #pragma unroll
    for (int i = 0; i < 4; i++)
        #pragma unroll
        for (int j = 0; j < 8; j++)
            #pragma unroll
            for (int r = 0; r < 4; r++) acc[i][j][r] = 0.0f;

    for (int kt = 0; kt < NKIT; kt++) {
        const int s = kt & 1;

        // Fill stage s^1 with tile kt+1 (readers done at iter kt-1, before the
        // barrier that admitted us — two-stage invariant). The 4-kk mma block
        // below (~2x longer than BK=32) covers the copy latency.
        if (kt + 1 < NKIT) {
            const int k0 = (kt + 1) * BK;
            const uint32_t sa = (uint32_t)((s ^ 1) * A_STAGE_B);
            const uint32_t sb = (uint32_t)((s ^ 1) * B_STAGE_B);
            #pragma unroll
            for (int j = 0; j < 8; j++) {
                cpa16(dstA[j] + sa, Abase + off[j] + k0);
                cpa16(dstB[j] + sb, Bbase + off[j] + k0);
            }
        }
        CPA_COMMIT();

        #pragma unroll
        for (int kk = 0; kk < 4; kk++) {           // four k16 steps per BK=64
            uint32_t a[4][4], b[4][4];
            #pragma unroll
            for (int ti = 0; ti < 4; ti++)
                ldsm_x4(a[ti], saddrA[s] + (uint32_t)(ti * 16 * LD + kk * 16) * 2u);
            #pragma unroll
            for (int p = 0; p < 4; p++)            // pair p covers n8-tiles 2p, 2p+1
                ldsm_x4(b[p], saddrB[s] + (uint32_t)(p * 16 * LD + kk * 16) * 2u);
            #pragma unroll
            for (int ti = 0; ti < 4; ti++) {
                #pragma unroll
                for (int tj = 0; tj < 8; tj++) {
                    const int p = tj >> 1, h = (tj & 1) * 2;
                    asm volatile(
                        "mma.sync.aligned.m16n8k16.row.col.f32.bf16.bf16.f32 "
                        "{%0,%1,%2,%3}, {%4,%5,%6,%7}, {%8,%9}, {%0,%1,%2,%3};\n"
                        : "+f"(acc[ti][tj][0]), "+f"(acc[ti][tj][1]),
                          "+f"(acc[ti][tj][2]), "+f"(acc[ti][tj][3])
                        : "r"(a[ti][0]), "r"(a[ti][1]), "r"(a[ti][2]), "r"(a[ti][3]),
                          "r"(b[p][h]), "r"(b[p][h + 1]));
                }
            }
        }

        // Stage s^1 copy complete, then publish to all warps.
        CPA_WAIT0();
        __syncthreads();
    }

    #pragma unroll
    for (int ti = 0; ti < 4; ti++) {
        #pragma unroll
        for (int tj = 0; tj < 8; tj++) {
            int r = bM + wm * 64 + ti * 16 + g;
            int c = bN + wn * 64 + tj * 8 + tg * 2;
            float2 lo = make_float2(acc[ti][tj][0], acc[ti][tj][1]);
            float2 hi = make_float2(acc[ti][tj][2], acc[ti][tj][3]);
            *reinterpret_cast<float2*>(&C[(size_t)r * NDIM + c]) = lo;
            *reinterpret_cast<float2*>(&C[(size_t)(r + 8) * NDIM + c]) = hi;
        }
    }
}

// ---------------------------------------------------------------------------
extern "C" void kernel_launch(void* const* d_in, const int* in_sizes, int n_in,
                              void* d_out, int out_size) {
    const float* x  = nullptr;
    const int*   wp = nullptr;
    const int*   ws = nullptr;
    for (int i = 0; i < n_in; i++) {
        if      (in_sizes[i] == MDIM * KDIM)      x  = (const float*)d_in[i];
        else if (in_sizes[i] == NDIM * KDIM / 2)  wp = (const int*)d_in[i];
        else if (in_sizes[i] == NDIM * KDIM / 32) ws = (const int*)d_in[i];
    }
    if (!x || !wp || !ws) {
        x  = (const float*)d_in[0];
        wp = (const int*)d_in[1];
        ws = (const int*)d_in[2];
    }

    // Fused pre-pass: one launch covers qdq(x) and wdq(W).
    prep_kernel<<<QDQ_BLOCKS + WDQ_BLOCKS, 256>>>(x, wp, ws);

    cudaFuncSetAttribute(gemm_kernel, cudaFuncAttributeMaxDynamicSharedMemorySize, SMEM_TOT);
    dim3 grid(NDIM / BN, MDIM / BM);
    gemm_kernel<<<grid, NTHR, SMEM_TOT>>>((float*)d_out);
}